// round 1
// baseline (speedup 1.0000x reference)
#include <cuda_runtime.h>
#include <math.h>

#define BATCH 8
#define H 1024
#define W 1024
#define NPIX (H*W)
#define RAD 2
#define TOPK 4096
#define CAP  262144   // per-batch candidate capacity (actual ~60k)

// ---------------- scratch (device globals: allocation-free rule) ----------------
__device__ float          g_A[BATCH*NPIX];       // separable maxpool temp
__device__ float          g_B[BATCH*NPIX];       // ss / mask-as-float field
__device__ unsigned char  g_flags[BATCH*NPIX];   // bit0 = mask, bit1 = supp
__device__ float          g_cval[BATCH*CAP];
__device__ int            g_cidx[BATCH*CAP];
__device__ int            g_ccnt[BATCH];
__device__ int            g_topk[BATCH*TOPK];

// ---------------- reset (graph replays must be deterministic) ----------------
__global__ void reset_kernel() {
    if (threadIdx.x < BATCH) g_ccnt[threadIdx.x] = 0;
}

// ---------------- separable 5x5 max with -inf (i.e., ignore-OOB) padding ----------------
__device__ __forceinline__ float hmax5(const float* row, int x) {
    float m = row[x];
    if (x >= 1)     m = fmaxf(m, row[x-1]);
    if (x >= 2)     m = fmaxf(m, row[x-2]);
    if (x <= W-2)   m = fmaxf(m, row[x+1]);
    if (x <= W-3)   m = fmaxf(m, row[x+2]);
    return m;
}

// src_sel: 0 -> external S, 1 -> g_B
__global__ void hmax_kernel(const float* __restrict__ S, int src_sel) {
    int i = blockIdx.x * blockDim.x + threadIdx.x;
    if (i >= BATCH*NPIX) return;
    const float* src = src_sel ? g_B : S;
    int x = i & (W-1);
    g_A[i] = hmax5(src + (i - x), x);
}

__device__ __forceinline__ float vmax5(const float* img, int y, int x) {
    float m = img[y*W + x];
    if (y >= 1)     m = fmaxf(m, img[(y-1)*W + x]);
    if (y >= 2)     m = fmaxf(m, img[(y-2)*W + x]);
    if (y <= H-2)   m = fmaxf(m, img[(y+1)*W + x]);
    if (y <= H-3)   m = fmaxf(m, img[(y+2)*W + x]);
    return m;
}

// vertical max of g_A + fused elementwise post-op
// mode 0: m0 = (S == maxpool(S));          flags.bit0 = m0; B = m0 ? 1 : 0
// mode 1: supp = maxpool(mask) > 0;        flags.bit1 = supp (keep bit0); B = supp ? 0 : S
// mode 2: new = (B==maxpool(B)) & !supp;   mask |= new;  flags.bit0 = mask; B = mask ? 1 : 0
// mode 3: same as 2 but final: collect candidates (mask & !border & S>0)
__global__ void vpost_kernel(const float* __restrict__ S, int mode) {
    int i = blockIdx.x * blockDim.x + threadIdx.x;
    if (i >= BATCH*NPIX) return;
    int x = i & (W-1);
    int y = (i >> 10) & (H-1);
    int b = i >> 20;
    const float* Ab = g_A + b*NPIX;
    float mp = vmax5(Ab, y, x);

    if (mode == 0) {
        bool m = (S[i] == mp);
        g_flags[i] = m ? 1 : 0;
        g_B[i] = m ? 1.f : 0.f;
    } else if (mode == 1) {
        bool supp = (mp > 0.f);
        g_flags[i] = (unsigned char)((g_flags[i] & 1) | (supp ? 2 : 0));
        g_B[i] = supp ? 0.f : S[i];
    } else if (mode == 2) {
        unsigned f = g_flags[i];
        bool m = (f & 1) || ((g_B[i] == mp) && !(f & 2));
        g_flags[i] = m ? 1 : 0;
        g_B[i] = m ? 1.f : 0.f;
    } else {
        unsigned f = g_flags[i];
        bool m = (f & 1) || ((g_B[i] == mp) && !(f & 2));
        if (m) {
            bool border = (x < RAD) | (x >= W-RAD) | (y < RAD) | (y >= H-RAD);
            float v = S[i];
            if (!border && v > 0.f) {
                int c = atomicAdd(&g_ccnt[b], 1);
                if (c < CAP) {
                    g_cval[b*CAP + c] = v;
                    g_cidx[b*CAP + c] = y*W + x;
                }
            }
        }
    }
}

// ---------------- exact top-k (value desc, index-asc tiebreak, jax.lax.top_k semantics) ----
__device__ __forceinline__ unsigned long long make_key(float v, int idx) {
    // positive floats are order-preserving as uint; distinct keys via ~idx
    return ((unsigned long long)__float_as_uint(v) << 32) |
           (unsigned long long)(0xFFFFFFFFu - (unsigned)idx);
}

__global__ void __launch_bounds__(1024) select_kernel() {
    __shared__ unsigned int hist[2048];
    __shared__ unsigned long long keys[TOPK];
    __shared__ unsigned long long s_hi;
    __shared__ int s_need, s_bin, s_cnt;

    int b = blockIdx.x, tid = threadIdx.x;
    int n = g_ccnt[b]; if (n > CAP) n = CAP;
    const float* cv = g_cval + b*CAP;
    const int*   ci = g_cidx + b*CAP;

    if (tid == 0) { s_hi = 0ull; s_need = TOPK; }
    __syncthreads();

    const int shifts[6] = {53, 42, 32, 21, 10, 0};
    const int nbits [6] = {11, 11, 10, 11, 11, 10};

    for (int lvl = 0; lvl < 6; lvl++) {
        int nb = nbits[lvl], sh = shifts[lvl], nbin = 1 << nb;
        for (int i = tid; i < nbin; i += 1024) hist[i] = 0;
        __syncthreads();
        unsigned long long hi = s_hi;
        for (int i = tid; i < n; i += 1024) {
            unsigned long long c = make_key(cv[i], ci[i]);
            if ((c >> (sh + nb)) == hi)
                atomicAdd(&hist[(unsigned)((c >> sh) & (unsigned long long)(nbin-1))], 1u);
        }
        __syncthreads();
        // inclusive suffix sums (Hillis-Steele)
        for (int off = 1; off < nbin; off <<= 1) {
            unsigned a0 = 0, a1 = 0;
            int i0 = tid, i1 = tid + 1024;
            if (i0 < nbin) a0 = hist[i0] + ((i0+off < nbin) ? hist[i0+off] : 0u);
            if (i1 < nbin) a1 = hist[i1] + ((i1+off < nbin) ? hist[i1+off] : 0u);
            __syncthreads();
            if (i0 < nbin) hist[i0] = a0;
            if (i1 < nbin) hist[i1] = a1;
            __syncthreads();
        }
        if (tid == 0) s_bin = -1;
        __syncthreads();
        int need = s_need;
        for (int i = tid; i < nbin; i += 1024) {
            unsigned Si = hist[i];
            unsigned Sn = (i+1 < nbin) ? hist[i+1] : 0u;
            if (Si >= (unsigned)need && Sn < (unsigned)need) s_bin = i;
        }
        __syncthreads();
        if (tid == 0) {
            int bin = s_bin;
            if (bin < 0) { bin = 0; s_need = (int)hist[0]; }   // fewer than needed remain
            else {
                unsigned above = (bin+1 < nbin) ? hist[bin+1] : 0u;
                s_need = s_need - (int)above;
            }
            s_hi = (s_hi << nb) | (unsigned long long)(unsigned)bin;
        }
        __syncthreads();
    }

    unsigned long long T = s_hi;  // exact 64-bit threshold key (keys distinct)
    if (tid == 0) s_cnt = 0;
    __syncthreads();
    for (int i = tid; i < n; i += 1024) {
        unsigned long long c = make_key(cv[i], ci[i]);
        if (c >= T) {
            int p = atomicAdd(&s_cnt, 1);
            if (p < TOPK) keys[p] = c;
        }
    }
    __syncthreads();
    int cnt = s_cnt; if (cnt > TOPK) cnt = TOPK;
    for (int i = tid; i < TOPK; i += 1024)
        if (i >= cnt) keys[i] = (unsigned long long)(0xFFFFFFFFu - (unsigned)i);  // val=0 pad
    __syncthreads();

    // bitonic sort ascending, read out reversed (=> descending)
    for (int k = 2; k <= TOPK; k <<= 1) {
        for (int j = k >> 1; j > 0; j >>= 1) {
            for (int t = tid; t < TOPK; t += 1024) {
                int p = t ^ j;
                if (p > t) {
                    unsigned long long a = keys[t], c2 = keys[p];
                    bool asc = ((t & k) == 0);
                    if ((a > c2) == asc) { keys[t] = c2; keys[p] = a; }
                }
            }
            __syncthreads();
        }
    }
    for (int i = tid; i < TOPK; i += 1024) {
        unsigned long long c = keys[TOPK-1-i];
        g_topk[b*TOPK + i] = (int)(0xFFFFFFFFu - (unsigned)(c & 0xFFFFFFFFull));
    }
}

// ---------------- refinement: softmax-argmax, dispersity, bilinear resample ----------------
__device__ __forceinline__ float bil_tap(const float* img, float xf, float yf, float wgt) {
    bool valid = (xf >= 0.f) & (xf < (float)W) & (yf >= 0.f) & (yf < (float)H);
    int xc = (int)fminf(fmaxf(xf, 0.f), (float)(W-1));
    int yc = (int)fminf(fmaxf(yf, 0.f), (float)(H-1));
    float s = valid ? img[yc*W + xc] : 0.f;
    return s * wgt;
}

__global__ void refine_kernel(const float* __restrict__ S, float* __restrict__ out) {
    int g = blockIdx.x * blockDim.x + threadIdx.x;
    if (g >= BATCH*TOPK) return;
    int b = g / TOPK;
    int idx = g_topk[g];
    int ix = idx & (W-1), iy = idx >> 10;
    const float* img = S + b*NPIX;

    float v[25];
    float mx = -1e30f;
    #pragma unroll
    for (int dy = 0; dy < 5; dy++) {
        int y = iy + dy - 2;
        #pragma unroll
        for (int dx = 0; dx < 5; dx++) {
            int x = ix + dx - 2;
            float val = (y >= 0 && y < H && x >= 0 && x < W) ? img[y*W + x] : 0.f;
            v[dy*5 + dx] = val;
            mx = fmaxf(mx, val);
        }
    }
    float e[25];
    float S0 = 0.f, Sx = 0.f, Sy = 0.f;
    #pragma unroll
    for (int p = 0; p < 25; p++) {
        float ee = expf((v[p] - mx) * 10.0f);   // /TEMPERATURE = *10
        e[p] = ee;
        S0 += ee;
        Sx += ee * (float)(p % 5 - 2);
        Sy += ee * (float)(p / 5 - 2);
    }
    float rx = Sx / S0, ry = Sy / S0;
    float disp = 0.f;
    #pragma unroll
    for (int p = 0; p < 25; p++) {
        float ddx = ((float)(p % 5 - 2) - rx) * 0.5f;  // /RADIUS
        float ddy = ((float)(p / 5 - 2) - ry) * 0.5f;
        disp += e[p] * (ddx*ddx + ddy*ddy);
    }
    disp /= S0;

    float kx = ((float)ix + rx) / (float)(W-1) * 2.f - 1.f;
    float ky = ((float)iy + ry) / (float)(H-1) * 2.f - 1.f;

    float px = (kx + 1.f) * 0.5f * (float)(W-1);
    float py = (ky + 1.f) * 0.5f * (float)(H-1);
    float x0 = floorf(px), y0 = floorf(py);
    float wx1 = px - x0, wx0 = 1.f - wx1;
    float wy1 = py - y0, wy0 = 1.f - wy1;
    float score = bil_tap(img, x0,     y0,     wx0*wy0)
                + bil_tap(img, x0+1.f, y0,     wx1*wy0)
                + bil_tap(img, x0,     y0+1.f, wx0*wy1)
                + bil_tap(img, x0+1.f, y0+1.f, wx1*wy1);

    // output layout: kp_xy[B,K,2] | kptscore[B,K] | dispersity[B,K]
    out[2*g + 0] = kx;
    out[2*g + 1] = ky;
    out[BATCH*TOPK*2 + g] = score;
    out[BATCH*TOPK*3 + g] = disp;
}

// ---------------- launch ----------------
extern "C" void kernel_launch(void* const* d_in, const int* in_sizes, int n_in,
                              void* d_out, int out_size) {
    const float* S = (const float*)d_in[0];
    float* out = (float*)d_out;

    const int threads = 256;
    const int blocks = (BATCH*NPIX + threads - 1) / threads;

    reset_kernel<<<1, 32>>>();

    // m0 = (S == maxpool(S))
    hmax_kernel<<<blocks, threads>>>(S, 0);
    vpost_kernel<<<blocks, threads>>>(S, 0);
    // iter 1: supp = dilate(m0); ss1
    hmax_kernel<<<blocks, threads>>>(S, 1);
    vpost_kernel<<<blocks, threads>>>(S, 1);
    // mask1 = m0 | (ss1==maxpool(ss1) & ~supp)
    hmax_kernel<<<blocks, threads>>>(S, 1);
    vpost_kernel<<<blocks, threads>>>(S, 2);
    // iter 2: supp2 = dilate(mask1); ss2
    hmax_kernel<<<blocks, threads>>>(S, 1);
    vpost_kernel<<<blocks, threads>>>(S, 1);
    // final mask + border cut + candidate compaction
    hmax_kernel<<<blocks, threads>>>(S, 1);
    vpost_kernel<<<blocks, threads>>>(S, 3);

    select_kernel<<<BATCH, 1024>>>();

    refine_kernel<<<(BATCH*TOPK + 255) / 256, 256>>>(S, out);
}

// round 2
// speedup vs baseline: 2.4573x; 2.4573x over previous
#include <cuda_runtime.h>
#include <math.h>

#define BATCH 8
#define H 1024
#define W 1024
#define NPIX (H*W)
#define TOPK 4096
#define CAP  262144
#define RS   84           // 64 tile + 2*10 halo
#define RS2  (RS*RS)
#define NT   512

typedef unsigned long long ull;

// ---------------- scratch ----------------
__device__ ull  g_ckey[(size_t)BATCH*CAP];
__device__ int  g_ccnt[BATCH];
__device__ int  g_topk[BATCH*TOPK];

__global__ void reset_kernel() {
    if (threadIdx.x < BATCH) g_ccnt[threadIdx.x] = 0;
}

// ---------------- fully fused NMS ----------------
template<int LO>
__device__ __forceinline__ void hmax_stage(const float* __restrict__ src,
                                           float* __restrict__ dst, int tid) {
    constexpr int Wd = RS - 2*LO;
    constexpr int YN = Wd + 4;
    for (int i = tid; i < YN*Wd; i += NT) {
        int ry = (LO-2) + i / Wd;
        int rx = LO + i % Wd;
        const float* r = src + ry*RS + rx;
        dst[ry*RS+rx] = fmaxf(fmaxf(fmaxf(r[-2],r[-1]), fmaxf(r[0],r[1])), r[2]);
    }
}

__device__ __forceinline__ float vmax_at(const float* __restrict__ t, int idx) {
    const float* c = t + idx;
    return fmaxf(fmaxf(fmaxf(c[-2*RS],c[-RS]), fmaxf(c[0],c[RS])), c[2*RS]);
}

__global__ __launch_bounds__(NT) void nms_fused(const float* __restrict__ S) {
    extern __shared__ float sh[];
    float* sS = sh;                // source scores (-INF outside image)
    float* sM = sh + RS2;          // mask field (1/0 in-image, -INF OOB)
    float* sF = sh + 2*RS2;        // suppressed-score field
    float* sT = sh + 3*RS2;        // separable temp
    unsigned char* sU = (unsigned char*)(sh + 4*RS2);   // supp flag
    __shared__ int s_cnt, s_base;

    int tid = threadIdx.x;
    int b = blockIdx.z;
    int tx0 = blockIdx.x*64 - 10, ty0 = blockIdx.y*64 - 10;
    const float* img = S + (size_t)b*NPIX;

    for (int i = tid; i < RS2; i += NT) {
        int ry = i/RS, rx = i - ry*RS;
        int gx = tx0+rx, gy = ty0+ry;
        bool in = ((unsigned)gx < W) & ((unsigned)gy < H);
        sS[i] = in ? __ldg(img + gy*W + gx) : -INFINITY;
    }
    if (tid == 0) s_cnt = 0;
    __syncthreads();

    // stage 1: m0 = (S == maxpool(S))
    hmax_stage<2>(sS, sT, tid); __syncthreads();
    {
        constexpr int Wd = RS-4;
        for (int i = tid; i < Wd*Wd; i += NT) {
            int ry = 2 + i/Wd, rx = 2 + i - (i/Wd)*Wd;
            int idx = ry*RS + rx;
            float s = sS[idx];
            float mp = vmax_at(sT, idx);
            sM[idx] = (s != -INFINITY) ? ((s == mp) ? 1.f : 0.f) : -INFINITY;
        }
    }
    __syncthreads();

    // stage 2: supp1 = maxpool(m0) > 0 ; ss1 = supp1 ? 0 : S
    hmax_stage<4>(sM, sT, tid); __syncthreads();
    {
        constexpr int Wd = RS-8;
        for (int i = tid; i < Wd*Wd; i += NT) {
            int ry = 4 + i/Wd, rx = 4 + i - (i/Wd)*Wd;
            int idx = ry*RS + rx;
            float s = sS[idx];
            bool supp = vmax_at(sT, idx) > 0.f;
            sU[idx] = supp;
            sF[idx] = (s != -INFINITY) ? (supp ? 0.f : s) : -INFINITY;
        }
    }
    __syncthreads();

    // stage 3: mask1 = m0 | ((ss1 == maxpool(ss1)) & ~supp1)
    hmax_stage<6>(sF, sT, tid); __syncthreads();
    {
        constexpr int Wd = RS-12;
        for (int i = tid; i < Wd*Wd; i += NT) {
            int ry = 6 + i/Wd, rx = 6 + i - (i/Wd)*Wd;
            int idx = ry*RS + rx;
            float s = sS[idx];
            float mp = vmax_at(sT, idx);
            bool nw = (sF[idx] == mp) && !sU[idx];
            bool m = (sM[idx] > 0.5f) || nw;
            sM[idx] = (s != -INFINITY) ? (m ? 1.f : 0.f) : -INFINITY;
        }
    }
    __syncthreads();

    // stage 4: supp2 = maxpool(mask1) > 0 ; ss2 = supp2 ? 0 : S
    hmax_stage<8>(sM, sT, tid); __syncthreads();
    {
        constexpr int Wd = RS-16;
        for (int i = tid; i < Wd*Wd; i += NT) {
            int ry = 8 + i/Wd, rx = 8 + i - (i/Wd)*Wd;
            int idx = ry*RS + rx;
            float s = sS[idx];
            bool supp = vmax_at(sT, idx) > 0.f;
            sU[idx] = supp;
            sF[idx] = (s != -INFINITY) ? (supp ? 0.f : s) : -INFINITY;
        }
    }
    __syncthreads();

    // stage 5: final mask + border + candidate compaction
    hmax_stage<10>(sF, sT, tid); __syncthreads();
    {
        ull lk[8]; int nk = 0;
        for (int i = tid; i < 64*64; i += NT) {
            int ry = 10 + (i >> 6), rx = 10 + (i & 63);
            int idx = ry*RS + rx;
            float s = sS[idx];
            float mp = vmax_at(sT, idx);
            bool nw = (sF[idx] == mp) && !sU[idx];
            bool m = (sM[idx] > 0.5f) || nw;
            int gx = tx0 + rx, gy = ty0 + ry;
            bool border = (gx < 2) | (gx >= W-2) | (gy < 2) | (gy >= H-2);
            if ((s != -INFINITY) & m & !border & (s > 0.f)) {
                lk[nk++] = ((ull)__float_as_uint(s) << 32) |
                           (ull)(0xFFFFFFFFu - (unsigned)(gy*W + gx));
            }
        }
        int p = nk ? atomicAdd(&s_cnt, nk) : 0;
        __syncthreads();
        if (tid == 0) s_base = atomicAdd(&g_ccnt[b], s_cnt);
        __syncthreads();
        int base = s_base;
        for (int j = 0; j < nk; j++) {
            int q = base + p + j;
            if (q < CAP) g_ckey[(size_t)b*CAP + q] = lk[j];
        }
    }
}

// ---------------- exact top-k (radix select over distinct 64-bit keys) ----------------
__global__ void __launch_bounds__(1024) select_kernel() {
    __shared__ unsigned int hist[2048];
    __shared__ ull keys[TOPK];
    __shared__ ull s_hi;
    __shared__ int s_need, s_bin, s_cnt;

    int b = blockIdx.x, tid = threadIdx.x;
    int n = g_ccnt[b]; if (n > CAP) n = CAP;
    const ull* ck = g_ckey + (size_t)b*CAP;

    if (tid == 0) { s_hi = 0ull; s_need = TOPK; }
    __syncthreads();

    const int shifts[6] = {53, 42, 32, 21, 10, 0};
    const int nbits [6] = {11, 11, 10, 11, 11, 10};

    for (int lvl = 0; lvl < 6; lvl++) {
        int nb = nbits[lvl], sh = shifts[lvl], nbin = 1 << nb;
        for (int i = tid; i < nbin; i += 1024) hist[i] = 0;
        __syncthreads();
        ull hi = s_hi;
        for (int i = tid; i < n; i += 1024) {
            ull c = ck[i];
            if ((c >> (sh + nb)) == hi)
                atomicAdd(&hist[(unsigned)((c >> sh) & (ull)(nbin-1))], 1u);
        }
        __syncthreads();
        for (int off = 1; off < nbin; off <<= 1) {
            unsigned a0 = 0, a1 = 0;
            int i0 = tid, i1 = tid + 1024;
            if (i0 < nbin) a0 = hist[i0] + ((i0+off < nbin) ? hist[i0+off] : 0u);
            if (i1 < nbin) a1 = hist[i1] + ((i1+off < nbin) ? hist[i1+off] : 0u);
            __syncthreads();
            if (i0 < nbin) hist[i0] = a0;
            if (i1 < nbin) hist[i1] = a1;
            __syncthreads();
        }
        if (tid == 0) s_bin = -1;
        __syncthreads();
        int need = s_need;
        for (int i = tid; i < nbin; i += 1024) {
            unsigned Si = hist[i];
            unsigned Sn = (i+1 < nbin) ? hist[i+1] : 0u;
            if (Si >= (unsigned)need && Sn < (unsigned)need) s_bin = i;
        }
        __syncthreads();
        if (tid == 0) {
            int bin = s_bin;
            if (bin < 0) { bin = 0; s_need = (int)hist[0]; }
            else {
                unsigned above = (bin+1 < nbin) ? hist[bin+1] : 0u;
                s_need = s_need - (int)above;
            }
            s_hi = (s_hi << nb) | (ull)(unsigned)bin;
        }
        __syncthreads();
    }

    ull T = s_hi;
    if (tid == 0) s_cnt = 0;
    __syncthreads();
    for (int i = tid; i < n; i += 1024) {
        ull c = ck[i];
        if (c >= T) {
            int p = atomicAdd(&s_cnt, 1);
            if (p < TOPK) keys[p] = c;
        }
    }
    __syncthreads();
    int cnt = s_cnt; if (cnt > TOPK) cnt = TOPK;
    for (int i = tid; i < TOPK; i += 1024)
        if (i >= cnt) keys[i] = (ull)(0xFFFFFFFFu - (unsigned)i);
    __syncthreads();

    for (int k = 2; k <= TOPK; k <<= 1) {
        for (int j = k >> 1; j > 0; j >>= 1) {
            for (int t = tid; t < TOPK; t += 1024) {
                int p = t ^ j;
                if (p > t) {
                    ull a = keys[t], c2 = keys[p];
                    bool asc = ((t & k) == 0);
                    if ((a > c2) == asc) { keys[t] = c2; keys[p] = a; }
                }
            }
            __syncthreads();
        }
    }
    for (int i = tid; i < TOPK; i += 1024) {
        ull c = keys[TOPK-1-i];
        g_topk[b*TOPK + i] = (int)(0xFFFFFFFFu - (unsigned)(c & 0xFFFFFFFFull));
    }
}

// ---------------- refinement ----------------
__device__ __forceinline__ float bil_tap(const float* img, float xf, float yf, float wgt) {
    bool valid = (xf >= 0.f) & (xf < (float)W) & (yf >= 0.f) & (yf < (float)H);
    int xc = (int)fminf(fmaxf(xf, 0.f), (float)(W-1));
    int yc = (int)fminf(fmaxf(yf, 0.f), (float)(H-1));
    float s = valid ? img[yc*W + xc] : 0.f;
    return s * wgt;
}

__global__ void refine_kernel(const float* __restrict__ S, float* __restrict__ out) {
    int g = blockIdx.x * blockDim.x + threadIdx.x;
    if (g >= BATCH*TOPK) return;
    int b = g / TOPK;
    int idx = g_topk[g];
    int ix = idx & (W-1), iy = idx >> 10;
    const float* img = S + (size_t)b*NPIX;

    float v[25];
    float mx = -1e30f;
    #pragma unroll
    for (int dy = 0; dy < 5; dy++) {
        int y = iy + dy - 2;
        #pragma unroll
        for (int dx = 0; dx < 5; dx++) {
            int x = ix + dx - 2;
            float val = (y >= 0 && y < H && x >= 0 && x < W) ? __ldg(img + y*W + x) : 0.f;
            v[dy*5 + dx] = val;
            mx = fmaxf(mx, val);
        }
    }
    float e[25];
    float S0 = 0.f, Sx = 0.f, Sy = 0.f;
    #pragma unroll
    for (int p = 0; p < 25; p++) {
        float ee = expf((v[p] - mx) * 10.0f);
        e[p] = ee;
        S0 += ee;
        Sx += ee * (float)(p % 5 - 2);
        Sy += ee * (float)(p / 5 - 2);
    }
    float rx = Sx / S0, ry = Sy / S0;
    float disp = 0.f;
    #pragma unroll
    for (int p = 0; p < 25; p++) {
        float ddx = ((float)(p % 5 - 2) - rx) * 0.5f;
        float ddy = ((float)(p / 5 - 2) - ry) * 0.5f;
        disp += e[p] * (ddx*ddx + ddy*ddy);
    }
    disp /= S0;

    float kx = ((float)ix + rx) / (float)(W-1) * 2.f - 1.f;
    float ky = ((float)iy + ry) / (float)(H-1) * 2.f - 1.f;

    float px = (kx + 1.f) * 0.5f * (float)(W-1);
    float py = (ky + 1.f) * 0.5f * (float)(H-1);
    float x0 = floorf(px), y0 = floorf(py);
    float wx1 = px - x0, wx0 = 1.f - wx1;
    float wy1 = py - y0, wy0 = 1.f - wy1;
    float score = bil_tap(img, x0,     y0,     wx0*wy0)
                + bil_tap(img, x0+1.f, y0,     wx1*wy0)
                + bil_tap(img, x0,     y0+1.f, wx0*wy1)
                + bil_tap(img, x0+1.f, y0+1.f, wx1*wy1);

    out[2*g + 0] = kx;
    out[2*g + 1] = ky;
    out[BATCH*TOPK*2 + g] = score;
    out[BATCH*TOPK*3 + g] = disp;
}

// ---------------- launch ----------------
extern "C" void kernel_launch(void* const* d_in, const int* in_sizes, int n_in,
                              void* d_out, int out_size) {
    const float* S = (const float*)d_in[0];
    float* out = (float*)d_out;

    const int smem_bytes = 4*RS2*sizeof(float) + RS2;  // 119952
    static int attr_set = 0;
    if (!attr_set) {
        cudaFuncSetAttribute(nms_fused, cudaFuncAttributeMaxDynamicSharedMemorySize, smem_bytes);
        attr_set = 1;
    }

    reset_kernel<<<1, 32>>>();
    dim3 grid(16, 16, 8);
    nms_fused<<<grid, NT, smem_bytes>>>(S);
    select_kernel<<<BATCH, 1024>>>();
    refine_kernel<<<(BATCH*TOPK + 255) / 256, 256>>>(S, out);
}

// round 4
// speedup vs baseline: 3.0120x; 1.2257x over previous
#include <cuda_runtime.h>
#include <math.h>

#define BATCH 8
#define H 1024
#define W 1024
#define NPIX (H*W)
#define TOPK 4096
#define CAP  262144
#define RS   84           // 64 tile + 2*10 halo
#define RS2  (RS*RS)
#define NT   512
#define NBIN 65536
#define CCAP 6144         // compaction capacity per batch
#define SORTN 8192
#define ULIM 0x30000000u  // (0x60<<23): values below 2^-31 collapse to bin 0

typedef unsigned long long ull;

// ---------------- scratch ----------------
__device__ ull      g_ckey[(size_t)BATCH*CAP];
__device__ int      g_ccnt[BATCH];
__device__ unsigned g_hist[BATCH*NBIN];
__device__ ull      g_comp[BATCH*SORTN];
__device__ int      g_compcnt[BATCH];
__device__ unsigned g_ulo[BATCH];
__device__ int      g_flag[BATCH];
__device__ int      g_topk[BATCH*TOPK];

__global__ void reset_kernel() {
    int i = blockIdx.x*1024 + threadIdx.x;
    if (i < BATCH*NBIN) g_hist[i] = 0u;
    if (i < BATCH) g_ccnt[i] = 0;
}

// ---------------- fused NMS ----------------
template<int LO>
__device__ __forceinline__ void hmax_f(const float* __restrict__ src,
                                       float* __restrict__ dst, int tid) {
    constexpr int Wd = RS - 2*LO;
    constexpr int YN = Wd + 4;
    for (int i = tid; i < YN*Wd; i += NT) {
        int ry = (LO-2) + i / Wd;
        int rx = LO + i % Wd;
        const float* r = src + ry*RS + rx;
        dst[ry*RS+rx] = fmaxf(fmaxf(fmaxf(r[-2],r[-1]), fmaxf(r[0],r[1])), r[2]);
    }
}

template<int LO>
__device__ __forceinline__ void hmax_b(const unsigned char* __restrict__ src,
                                       float* __restrict__ dst, int tid) {
    constexpr int Wd = RS - 2*LO;
    constexpr int YN = Wd + 4;
    for (int i = tid; i < YN*Wd; i += NT) {
        int ry = (LO-2) + i / Wd;
        int rx = LO + i % Wd;
        const unsigned char* r = src + ry*RS + rx;
        unsigned m = max(max(max((unsigned)r[-2],(unsigned)r[-1]),
                             max((unsigned)r[0],(unsigned)r[1])), (unsigned)r[2]);
        dst[ry*RS+rx] = (float)m;
    }
}

__device__ __forceinline__ float vmax_at(const float* __restrict__ t, int idx) {
    const float* c = t + idx;
    return fmaxf(fmaxf(fmaxf(c[-2*RS],c[-RS]), fmaxf(c[0],c[RS])), c[2*RS]);
}

__global__ __launch_bounds__(NT, 2) void nms_fused(const float* __restrict__ S) {
    extern __shared__ float sh[];
    float* sS = sh;                 // scores (0 outside image)
    float* sF = sh + RS2;           // suppressed-score field
    float* sT = sh + 2*RS2;         // separable temp
    unsigned char* sM = (unsigned char*)(sh + 3*RS2);           // mask
    unsigned char* sU = (unsigned char*)(sh + 3*RS2) + RS2;     // supp
    __shared__ int s_cnt, s_base;

    int tid = threadIdx.x;
    int b = blockIdx.z;
    int tx0 = blockIdx.x*64 - 10, ty0 = blockIdx.y*64 - 10;
    const float* img = S + (size_t)b*NPIX;

    for (int i = tid; i < RS2; i += NT) {
        int ry = i/RS, rx = i - ry*RS;
        int gx = tx0+rx, gy = ty0+ry;
        bool in = ((unsigned)gx < W) & ((unsigned)gy < H);
        sS[i] = in ? __ldg(img + gy*W + gx) : 0.f;
    }
    if (tid == 0) s_cnt = 0;
    __syncthreads();

    // stage 1: m0 = in && (S == maxpool(S))
    hmax_f<2>(sS, sT, tid); __syncthreads();
    {
        constexpr int Wd = RS-4;
        for (int i = tid; i < Wd*Wd; i += NT) {
            int ry = 2 + i/Wd, rx = 2 + i - (i/Wd)*Wd;
            int idx = ry*RS + rx;
            bool in = ((unsigned)(tx0+rx) < W) & ((unsigned)(ty0+ry) < H);
            sM[idx] = (unsigned char)(in && (sS[idx] == vmax_at(sT, idx)));
        }
    }
    __syncthreads();

    // stage 2: supp1 = maxpool(m0) > 0 ; ss1 = supp1 ? 0 : S
    hmax_b<4>(sM, sT, tid); __syncthreads();
    {
        constexpr int Wd = RS-8;
        for (int i = tid; i < Wd*Wd; i += NT) {
            int ry = 4 + i/Wd, rx = 4 + i - (i/Wd)*Wd;
            int idx = ry*RS + rx;
            bool supp = vmax_at(sT, idx) > 0.f;
            sU[idx] = (unsigned char)supp;
            sF[idx] = supp ? 0.f : sS[idx];
        }
    }
    __syncthreads();

    // stage 3: mask1 = m0 | ((ss1 == maxpool(ss1)) & ~supp1), gated in-image
    hmax_f<6>(sF, sT, tid); __syncthreads();
    {
        constexpr int Wd = RS-12;
        for (int i = tid; i < Wd*Wd; i += NT) {
            int ry = 6 + i/Wd, rx = 6 + i - (i/Wd)*Wd;
            int idx = ry*RS + rx;
            bool in = ((unsigned)(tx0+rx) < W) & ((unsigned)(ty0+ry) < H);
            bool nw = (sF[idx] == vmax_at(sT, idx)) && !sU[idx];
            sM[idx] = (unsigned char)(in && (sM[idx] || nw));
        }
    }
    __syncthreads();

    // stage 4: supp2 = maxpool(mask1) > 0 ; ss2 = supp2 ? 0 : S
    hmax_b<8>(sM, sT, tid); __syncthreads();
    {
        constexpr int Wd = RS-16;
        for (int i = tid; i < Wd*Wd; i += NT) {
            int ry = 8 + i/Wd, rx = 8 + i - (i/Wd)*Wd;
            int idx = ry*RS + rx;
            bool supp = vmax_at(sT, idx) > 0.f;
            sU[idx] = (unsigned char)supp;
            sF[idx] = supp ? 0.f : sS[idx];
        }
    }
    __syncthreads();

    // stage 5: final mask + border + compaction + value histogram
    hmax_f<10>(sF, sT, tid); __syncthreads();
    {
        ull lk[8]; int nk = 0;
        for (int i = tid; i < 64*64; i += NT) {
            int ry = 10 + (i >> 6), rx = 10 + (i & 63);
            int idx = ry*RS + rx;
            float s = sS[idx];
            bool nw = (sF[idx] == vmax_at(sT, idx)) && !sU[idx];
            bool m = sM[idx] || nw;
            int gx = tx0 + rx, gy = ty0 + ry;
            bool border = (gx < 2) | (gx >= W-2) | (gy < 2) | (gy >= H-2);
            if (m & !border & (s > 0.f)) {
                unsigned u = __float_as_uint(s);
                unsigned bin = (u >= ULIM) ? ((u >> 12) & 0xFFFFu) : 0u;
                atomicAdd(&g_hist[b*NBIN + bin], 1u);
                lk[nk++] = ((ull)u << 32) |
                           (ull)(0xFFFFFFFFu - (unsigned)(gy*W + gx));
            }
        }
        int p = nk ? atomicAdd(&s_cnt, nk) : 0;
        __syncthreads();
        if (tid == 0) s_base = atomicAdd(&g_ccnt[b], s_cnt);
        __syncthreads();
        int base = s_base;
        for (int j = 0; j < nk; j++) {
            int q = base + p + j;
            if (q < CAP) g_ckey[(size_t)b*CAP + q] = lk[j];
        }
    }
}

// ---------------- per-batch exact threshold from histogram ----------------
__global__ void __launch_bounds__(1024) threshold_kernel() {
    __shared__ unsigned part[1024];
    __shared__ int s_seg;
    int b = blockIdx.x, tid = threadIdx.x;
    const unsigned* hist = g_hist + b*NBIN;

    unsigned s = 0;
    #pragma unroll 8
    for (int j = 0; j < 64; j++) s += hist[tid*64 + j];
    part[tid] = s;
    __syncthreads();
    // inclusive suffix scan
    for (int off = 1; off < 1024; off <<= 1) {
        unsigned v = part[tid] + ((tid+off < 1024) ? part[tid+off] : 0u);
        __syncthreads();
        part[tid] = v;
        __syncthreads();
    }
    unsigned total = part[0];
    unsigned need = total < (unsigned)TOPK ? total : (unsigned)TOPK;

    if (tid == 0) s_seg = -1;
    __syncthreads();
    if (total > (unsigned)CCAP) {
        if (part[tid] >= need && (tid == 1023 || part[tid+1] < need)) s_seg = tid;
    }
    __syncthreads();

    if (tid == 0) {
        int flag = 0; unsigned u_lo = 0;
        if (total > (unsigned)CCAP) {
            int seg = s_seg;
            unsigned running = (seg < 1023) ? part[seg+1] : 0u;
            int bin = -1; unsigned cnt = 0;
            for (int j = 63; j >= 0; j--) {
                running += hist[seg*64 + j];
                if (running >= need) { bin = seg*64 + j; cnt = running; break; }
            }
            if (bin <= 0 || cnt > (unsigned)CCAP) flag = 1;
            else u_lo = (((unsigned)bin) << 12) | ULIM;   // FIX: restore high bits
        }
        g_ulo[b] = u_lo;
        g_flag[b] = flag;
        g_compcnt[b] = 0;
    }
}

// ---------------- parallel compaction of candidates >= threshold ----------------
__global__ void compact_kernel() {
    int b = blockIdx.y;
    if (g_flag[b]) return;
    int n = g_ccnt[b]; if (n > CAP) n = CAP;
    unsigned u_lo = g_ulo[b];
    const ull* ck = g_ckey + (size_t)b*CAP;
    int tid = threadIdx.x;
    int lane = tid & 31;
    int stride = gridDim.x * blockDim.x;
    int iters = (n + stride - 1) / stride;
    for (int j = 0; j < iters; j++) {
        int i = blockIdx.x*blockDim.x + tid + j*stride;
        ull k = 0; bool take = false;
        if (i < n) {
            k = ck[i];
            take = ((unsigned)(k >> 32)) >= u_lo;
        }
        unsigned m = __ballot_sync(0xFFFFFFFFu, take);
        if (m) {
            int leader = __ffs(m) - 1;
            int cnt = __popc(m);
            int base = 0;
            if (lane == leader) base = atomicAdd(&g_compcnt[b], cnt);
            base = __shfl_sync(0xFFFFFFFFu, base, leader);
            if (take) {
                int p = base + __popc(m & ((1u << lane) - 1));
                if (p < SORTN) g_comp[b*SORTN + p] = k;
            }
        }
    }
}

// ---------------- per-batch sort of compacted keys (+ exact fallback) ----------------
__global__ void __launch_bounds__(1024) sort_kernel() {
    extern __shared__ ull keys[];      // SORTN entries (64KB)
    __shared__ unsigned fhist[2048];
    __shared__ ull s_hi;
    __shared__ int s_need, s_bin, s_cnt2;

    int b = blockIdx.x, tid = threadIdx.x;

    if (!g_flag[b]) {
        int M = g_compcnt[b]; if (M > SORTN) M = SORTN;
        for (int i = tid; i < SORTN; i += 1024)
            keys[i] = (i < M) ? g_comp[b*SORTN + i]
                              : (ull)(0xFFFFFFFFu - (unsigned)(i - M));
        __syncthreads();
        for (int k = 2; k <= SORTN; k <<= 1) {
            for (int j = k >> 1; j > 0; j >>= 1) {
                for (int t = tid; t < SORTN; t += 1024) {
                    int p = t ^ j;
                    if (p > t) {
                        ull a = keys[t], c2 = keys[p];
                        bool asc = ((t & k) == 0);
                        if ((a > c2) == asc) { keys[t] = c2; keys[p] = a; }
                    }
                }
                __syncthreads();
            }
        }
        for (int i = tid; i < TOPK; i += 1024) {
            ull c = keys[SORTN-1-i];
            g_topk[b*TOPK + i] = (int)(0xFFFFFFFFu - (unsigned)(c & 0xFFFFFFFFull));
        }
        return;
    }

    // ---- fallback: exact 6-level radix select over raw candidates ----
    int n = g_ccnt[b]; if (n > CAP) n = CAP;
    const ull* ck = g_ckey + (size_t)b*CAP;
    if (tid == 0) { s_hi = 0ull; s_need = TOPK; }
    __syncthreads();
    const int shifts[6] = {53, 42, 32, 21, 10, 0};
    const int nbits [6] = {11, 11, 10, 11, 11, 10};
    for (int lvl = 0; lvl < 6; lvl++) {
        int nb = nbits[lvl], sh = shifts[lvl], nbin = 1 << nb;
        for (int i = tid; i < nbin; i += 1024) fhist[i] = 0;
        __syncthreads();
        ull hi = s_hi;
        for (int i = tid; i < n; i += 1024) {
            ull c = ck[i];
            if ((c >> (sh + nb)) == hi)
                atomicAdd(&fhist[(unsigned)((c >> sh) & (ull)(nbin-1))], 1u);
        }
        __syncthreads();
        for (int off = 1; off < nbin; off <<= 1) {
            unsigned a0 = 0, a1 = 0;
            int i0 = tid, i1 = tid + 1024;
            if (i0 < nbin) a0 = fhist[i0] + ((i0+off < nbin) ? fhist[i0+off] : 0u);
            if (i1 < nbin) a1 = fhist[i1] + ((i1+off < nbin) ? fhist[i1+off] : 0u);
            __syncthreads();
            if (i0 < nbin) fhist[i0] = a0;
            if (i1 < nbin) fhist[i1] = a1;
            __syncthreads();
        }
        if (tid == 0) s_bin = -1;
        __syncthreads();
        int need = s_need;
        for (int i = tid; i < nbin; i += 1024) {
            unsigned Si = fhist[i];
            unsigned Sn = (i+1 < nbin) ? fhist[i+1] : 0u;
            if (Si >= (unsigned)need && Sn < (unsigned)need) s_bin = i;
        }
        __syncthreads();
        if (tid == 0) {
            int bin = s_bin;
            if (bin < 0) { bin = 0; s_need = (int)fhist[0]; }
            else {
                unsigned above = (bin+1 < nbin) ? fhist[bin+1] : 0u;
                s_need = s_need - (int)above;
            }
            s_hi = (s_hi << nb) | (ull)(unsigned)bin;
        }
        __syncthreads();
    }
    ull T = s_hi;
    if (tid == 0) s_cnt2 = 0;
    __syncthreads();
    for (int i = tid; i < n; i += 1024) {
        ull c = ck[i];
        if (c >= T) {
            int p = atomicAdd(&s_cnt2, 1);
            if (p < TOPK) keys[p] = c;
        }
    }
    __syncthreads();
    int cnt = s_cnt2; if (cnt > TOPK) cnt = TOPK;
    for (int i = tid; i < TOPK; i += 1024)
        if (i >= cnt) keys[i] = (ull)(0xFFFFFFFFu - (unsigned)i);
    __syncthreads();
    for (int k = 2; k <= TOPK; k <<= 1) {
        for (int j = k >> 1; j > 0; j >>= 1) {
            for (int t = tid; t < TOPK; t += 1024) {
                int p = t ^ j;
                if (p > t) {
                    ull a = keys[t], c2 = keys[p];
                    bool asc = ((t & k) == 0);
                    if ((a > c2) == asc) { keys[t] = c2; keys[p] = a; }
                }
            }
            __syncthreads();
        }
    }
    for (int i = tid; i < TOPK; i += 1024) {
        ull c = keys[TOPK-1-i];
        g_topk[b*TOPK + i] = (int)(0xFFFFFFFFu - (unsigned)(c & 0xFFFFFFFFull));
    }
}

// ---------------- refinement ----------------
__device__ __forceinline__ float bil_tap(const float* img, float xf, float yf, float wgt) {
    bool valid = (xf >= 0.f) & (xf < (float)W) & (yf >= 0.f) & (yf < (float)H);
    int xc = (int)fminf(fmaxf(xf, 0.f), (float)(W-1));
    int yc = (int)fminf(fmaxf(yf, 0.f), (float)(H-1));
    float s = valid ? img[yc*W + xc] : 0.f;
    return s * wgt;
}

__global__ void refine_kernel(const float* __restrict__ S, float* __restrict__ out) {
    int g = blockIdx.x * blockDim.x + threadIdx.x;
    if (g >= BATCH*TOPK) return;
    int b = g / TOPK;
    int idx = g_topk[g];
    int ix = idx & (W-1), iy = idx >> 10;
    const float* img = S + (size_t)b*NPIX;

    float v[25];
    float mx = -1e30f;
    #pragma unroll
    for (int dy = 0; dy < 5; dy++) {
        int y = iy + dy - 2;
        #pragma unroll
        for (int dx = 0; dx < 5; dx++) {
            int x = ix + dx - 2;
            float val = (y >= 0 && y < H && x >= 0 && x < W) ? __ldg(img + y*W + x) : 0.f;
            v[dy*5 + dx] = val;
            mx = fmaxf(mx, val);
        }
    }
    float e[25];
    float S0 = 0.f, Sx = 0.f, Sy = 0.f;
    #pragma unroll
    for (int p = 0; p < 25; p++) {
        float ee = expf((v[p] - mx) * 10.0f);
        e[p] = ee;
        S0 += ee;
        Sx += ee * (float)(p % 5 - 2);
        Sy += ee * (float)(p / 5 - 2);
    }
    float rx = Sx / S0, ry = Sy / S0;
    float disp = 0.f;
    #pragma unroll
    for (int p = 0; p < 25; p++) {
        float ddx = ((float)(p % 5 - 2) - rx) * 0.5f;
        float ddy = ((float)(p / 5 - 2) - ry) * 0.5f;
        disp += e[p] * (ddx*ddx + ddy*ddy);
    }
    disp /= S0;

    float kx = ((float)ix + rx) / (float)(W-1) * 2.f - 1.f;
    float ky = ((float)iy + ry) / (float)(H-1) * 2.f - 1.f;

    float px = (kx + 1.f) * 0.5f * (float)(W-1);
    float py = (ky + 1.f) * 0.5f * (float)(H-1);
    float x0 = floorf(px), y0 = floorf(py);
    float wx1 = px - x0, wx0 = 1.f - wx1;
    float wy1 = py - y0, wy0 = 1.f - wy1;
    float score = bil_tap(img, x0,     y0,     wx0*wy0)
                + bil_tap(img, x0+1.f, y0,     wx1*wy0)
                + bil_tap(img, x0,     y0+1.f, wx0*wy1)
                + bil_tap(img, x0+1.f, y0+1.f, wx1*wy1);

    out[2*g + 0] = kx;
    out[2*g + 1] = ky;
    out[BATCH*TOPK*2 + g] = score;
    out[BATCH*TOPK*3 + g] = disp;
}

// ---------------- launch ----------------
extern "C" void kernel_launch(void* const* d_in, const int* in_sizes, int n_in,
                              void* d_out, int out_size) {
    const float* S = (const float*)d_in[0];
    float* out = (float*)d_out;

    const int nms_smem  = 3*RS2*sizeof(float) + 2*RS2;   // 98784
    const int sort_smem = SORTN*sizeof(ull);             // 65536
    static int attr_set = 0;
    if (!attr_set) {
        cudaFuncSetAttribute(nms_fused, cudaFuncAttributeMaxDynamicSharedMemorySize, nms_smem);
        cudaFuncSetAttribute(sort_kernel, cudaFuncAttributeMaxDynamicSharedMemorySize, sort_smem);
        attr_set = 1;
    }

    reset_kernel<<<512, 1024>>>();
    dim3 grid(16, 16, 8);
    nms_fused<<<grid, NT, nms_smem>>>(S);
    threshold_kernel<<<BATCH, 1024>>>();
    compact_kernel<<<dim3(16, BATCH), 256>>>();
    sort_kernel<<<BATCH, 1024, sort_smem>>>();
    refine_kernel<<<(BATCH*TOPK + 255) / 256, 256>>>(S, out);
}

// round 5
// speedup vs baseline: 3.4373x; 1.1412x over previous
#include <cuda_runtime.h>
#include <math.h>

#define BATCH 8
#define H 1024
#define W 1024
#define NPIX (H*W)
#define TOPK 4096
#define CAP  262144
#define RS   84           // 64 tile + 2*10 halo
#define RS2  (RS*RS)
#define NT   512
#define NBIN 65536
#define CCAP 6144
#define SORTN 8192
#define ULIM 0x30000000u

typedef unsigned long long ull;
typedef unsigned int uint;

// ---------------- scratch ----------------
__device__ ull      g_ckey[(size_t)BATCH*CAP];
__device__ int      g_ccnt[BATCH];
__device__ unsigned g_hist[BATCH*NBIN];
__device__ ull      g_comp[BATCH*SORTN];
__device__ int      g_compcnt[BATCH];
__device__ unsigned g_ulo[BATCH];
__device__ int      g_flag[BATCH];
__device__ int      g_topk[BATCH*TOPK];

__global__ void reset_kernel() {
    int i = blockIdx.x*1024 + threadIdx.x;
    uint4* h4 = (uint4*)g_hist;
    if (i < BATCH*NBIN/4) h4[i] = make_uint4(0,0,0,0);
    if (i < BATCH) g_ccnt[i] = 0;
}

// ---------------- fused NMS: 4-wide stencil stages ----------------
// horizontal 5-tap max over floats, outputs x in [LO, RS-LO), rows [LO-2, RS-LO+2)
// requires LO % 4 == 2 for float4 alignment (LO in {2,6,10})
template<int LO>
__device__ __forceinline__ void hmax_f4(const float* __restrict__ src,
                                        float* __restrict__ dst, int tid) {
    static_assert((LO & 3) == 2, "alignment");
    constexpr int Wd = RS - 2*LO;
    constexpr int NC = Wd/4;
    constexpr int YN = Wd + 4;
    for (int c = tid; c < YN*NC; c += NT) {
        int ry = (LO-2) + c / NC;
        int cx = LO + (c % NC)*4;
        const float* p = src + ry*RS + (cx-2);
        float4 A = *(const float4*)p;
        float4 B = *(const float4*)(p+4);
        float m12 = fmaxf(A.y, A.z);
        float m34 = fmaxf(A.w, B.x);
        float m56 = fmaxf(B.y, B.z);
        float* q = dst + ry*RS + cx;
        q[0] = fmaxf(fmaxf(A.x, m12), m34);
        q[1] = fmaxf(fmaxf(m12, m34), B.y);
        q[2] = fmaxf(fmaxf(A.z, m34), m56);
        q[3] = fmaxf(fmaxf(m34, m56), B.w);
    }
}

// horizontal 5-tap OR over 0/1 bytes (mask dilation), packed output (LO in {4,8})
template<int LO>
__device__ __forceinline__ void hmax_b4(const unsigned char* __restrict__ src,
                                        unsigned char* __restrict__ dst, int tid) {
    static_assert((LO & 3) == 0, "alignment");
    constexpr int Wd = RS - 2*LO;
    constexpr int NC = Wd/4;
    constexpr int YN = Wd + 4;
    for (int c = tid; c < YN*NC; c += NT) {
        int ry = (LO-2) + c / NC;
        int cx = LO + (c % NC)*4;
        int base = ry*RS + cx;
        uint W0 = *(const uint*)(src + base - 4);
        uint W1 = *(const uint*)(src + base);
        uint W2 = *(const uint*)(src + base + 4);
        uint v1 = __byte_perm(W0, W1, 0x5432);
        uint v2 = __byte_perm(W0, W1, 0x6543);
        uint v4 = __byte_perm(W1, W2, 0x4321);
        uint v5 = __byte_perm(W1, W2, 0x5432);
        *(uint*)(dst + base) = v1 | v2 | W1 | v4 | v5;
    }
}

// 8-input -> 4-output vertical 5-tap max trees
#define VTREE_F(t, o) do { \
    float m12 = fmaxf(t[1], t[2]); \
    float m34 = fmaxf(t[3], t[4]); \
    float m56 = fmaxf(t[5], t[6]); \
    o[0] = fmaxf(fmaxf(t[0], m12), m34); \
    o[1] = fmaxf(fmaxf(m12, m34), t[5]); \
    o[2] = fmaxf(fmaxf(t[2], m34), m56); \
    o[3] = fmaxf(fmaxf(m34, m56), t[7]); \
} while(0)

__global__ __launch_bounds__(NT, 2) void nms_fused(const float* __restrict__ S) {
    extern __shared__ float sh[];
    float* sS = sh;                 // scores (0 outside image)
    float* sF = sh + RS2;           // suppressed-score field
    float* sT = sh + 2*RS2;         // separable temp (aliased as bytes for mask stages)
    unsigned char* sTb = (unsigned char*)sT;
    unsigned char* sM = (unsigned char*)(sh + 3*RS2);           // mask
    unsigned char* sU = (unsigned char*)(sh + 3*RS2) + RS2;     // supp
    __shared__ int s_cnt, s_base;

    int tid = threadIdx.x;
    int b = blockIdx.z;
    int tx0 = blockIdx.x*64 - 10, ty0 = blockIdx.y*64 - 10;
    const float* img = S + (size_t)b*NPIX;

    for (int i = tid; i < RS2; i += NT) {
        int ry = i/RS, rx = i - ry*RS;
        int gx = tx0+rx, gy = ty0+ry;
        bool in = ((unsigned)gx < W) & ((unsigned)gy < H);
        sS[i] = in ? __ldg(img + gy*W + gx) : 0.f;
    }
    if (tid == 0) s_cnt = 0;
    __syncthreads();

    // ---- stage 1: m0 = in && (S == maxpool(S)) ----
    hmax_f4<2>(sS, sT, tid); __syncthreads();
    {
        constexpr int LO = 2, Wd = RS - 2*LO;
        for (int c = tid; c < Wd*(Wd/4); c += NT) {
            int rx = LO + c % Wd;
            int ry0 = LO + (c / Wd)*4;
            float t[8], o[4];
            #pragma unroll
            for (int r = 0; r < 8; r++) t[r] = sT[(ry0-2+r)*RS + rx];
            VTREE_F(t, o);
            bool inx = ((unsigned)(tx0+rx) < W);
            #pragma unroll
            for (int r = 0; r < 4; r++) {
                int idx = (ry0+r)*RS + rx;
                bool in = inx & ((unsigned)(ty0+ry0+r) < H);
                sM[idx] = (unsigned char)(in && (sS[idx] == o[r]));
            }
        }
    }
    __syncthreads();

    // ---- stage 2: supp1 = dilate(m0) ; ss1 = supp1 ? 0 : S ----
    hmax_b4<4>(sM, sTb, tid); __syncthreads();
    {
        constexpr int LO = 4, Wd = RS - 2*LO;
        for (int c = tid; c < Wd*(Wd/4); c += NT) {
            int rx = LO + c % Wd;
            int ry0 = LO + (c / Wd)*4;
            unsigned t[8];
            #pragma unroll
            for (int r = 0; r < 8; r++) t[r] = sTb[(ry0-2+r)*RS + rx];
            unsigned m12 = t[1]|t[2], m34 = t[3]|t[4], m56 = t[5]|t[6];
            unsigned o[4] = { t[0]|m12|m34, m12|m34|t[5], t[2]|m34|m56, m34|m56|t[7] };
            #pragma unroll
            for (int r = 0; r < 4; r++) {
                int idx = (ry0+r)*RS + rx;
                bool supp = o[r] != 0u;
                sU[idx] = (unsigned char)supp;
                sF[idx] = supp ? 0.f : sS[idx];
            }
        }
    }
    __syncthreads();

    // ---- stage 3: mask1 = m0 | ((ss1 == maxpool(ss1)) & ~supp1) ----
    hmax_f4<6>(sF, sT, tid); __syncthreads();
    {
        constexpr int LO = 6, Wd = RS - 2*LO;
        for (int c = tid; c < Wd*(Wd/4); c += NT) {
            int rx = LO + c % Wd;
            int ry0 = LO + (c / Wd)*4;
            float t[8], o[4];
            #pragma unroll
            for (int r = 0; r < 8; r++) t[r] = sT[(ry0-2+r)*RS + rx];
            VTREE_F(t, o);
            bool inx = ((unsigned)(tx0+rx) < W);
            #pragma unroll
            for (int r = 0; r < 4; r++) {
                int idx = (ry0+r)*RS + rx;
                bool in = inx & ((unsigned)(ty0+ry0+r) < H);
                bool nw = (sF[idx] == o[r]) && !sU[idx];
                sM[idx] = (unsigned char)(in && (sM[idx] || nw));
            }
        }
    }
    __syncthreads();

    // ---- stage 4: supp2 = dilate(mask1) ; ss2 = supp2 ? 0 : S ----
    hmax_b4<8>(sM, sTb, tid); __syncthreads();
    {
        constexpr int LO = 8, Wd = RS - 2*LO;
        for (int c = tid; c < Wd*(Wd/4); c += NT) {
            int rx = LO + c % Wd;
            int ry0 = LO + (c / Wd)*4;
            unsigned t[8];
            #pragma unroll
            for (int r = 0; r < 8; r++) t[r] = sTb[(ry0-2+r)*RS + rx];
            unsigned m12 = t[1]|t[2], m34 = t[3]|t[4], m56 = t[5]|t[6];
            unsigned o[4] = { t[0]|m12|m34, m12|m34|t[5], t[2]|m34|m56, m34|m56|t[7] };
            #pragma unroll
            for (int r = 0; r < 4; r++) {
                int idx = (ry0+r)*RS + rx;
                bool supp = o[r] != 0u;
                sU[idx] = (unsigned char)supp;
                sF[idx] = supp ? 0.f : sS[idx];
            }
        }
    }
    __syncthreads();

    // ---- stage 5: final mask + border + compaction + value histogram ----
    hmax_f4<10>(sF, sT, tid); __syncthreads();
    {
        constexpr int LO = 10, Wd = RS - 2*LO;   // 64
        ull lk[8]; int nk = 0;
        for (int c = tid; c < Wd*(Wd/4); c += NT) {
            int rx = LO + c % Wd;
            int ry0 = LO + (c / Wd)*4;
            float t[8], o[4];
            #pragma unroll
            for (int r = 0; r < 8; r++) t[r] = sT[(ry0-2+r)*RS + rx];
            VTREE_F(t, o);
            int gx = tx0 + rx;
            bool bx = (gx < 2) | (gx >= W-2);
            #pragma unroll
            for (int r = 0; r < 4; r++) {
                int idx = (ry0+r)*RS + rx;
                float s = sS[idx];
                bool nw = (sF[idx] == o[r]) && !sU[idx];
                bool m = sM[idx] || nw;
                int gy = ty0 + ry0 + r;
                bool border = bx | (gy < 2) | (gy >= H-2);
                if (m & !border & (s > 0.f)) {
                    unsigned u = __float_as_uint(s);
                    unsigned bin = (u >= ULIM) ? ((u >> 12) & 0xFFFFu) : 0u;
                    atomicAdd(&g_hist[b*NBIN + bin], 1u);
                    lk[nk++] = ((ull)u << 32) |
                               (ull)(0xFFFFFFFFu - (unsigned)(gy*W + gx));
                }
            }
        }
        int p = nk ? atomicAdd(&s_cnt, nk) : 0;
        __syncthreads();
        if (tid == 0) s_base = atomicAdd(&g_ccnt[b], s_cnt);
        __syncthreads();
        int base = s_base;
        for (int j = 0; j < nk; j++) {
            int q = base + p + j;
            if (q < CAP) g_ckey[(size_t)b*CAP + q] = lk[j];
        }
    }
}

// ---------------- per-batch exact threshold from histogram ----------------
__global__ void __launch_bounds__(1024) threshold_kernel() {
    __shared__ unsigned part[1024];
    __shared__ int s_seg;
    int b = blockIdx.x, tid = threadIdx.x;
    const unsigned* hist = g_hist + b*NBIN;

    unsigned s = 0;
    #pragma unroll 8
    for (int j = 0; j < 64; j++) s += hist[tid*64 + j];
    part[tid] = s;
    __syncthreads();
    for (int off = 1; off < 1024; off <<= 1) {
        unsigned v = part[tid] + ((tid+off < 1024) ? part[tid+off] : 0u);
        __syncthreads();
        part[tid] = v;
        __syncthreads();
    }
    unsigned total = part[0];
    unsigned need = total < (unsigned)TOPK ? total : (unsigned)TOPK;

    if (tid == 0) s_seg = -1;
    __syncthreads();
    if (total > (unsigned)CCAP) {
        if (part[tid] >= need && (tid == 1023 || part[tid+1] < need)) s_seg = tid;
    }
    __syncthreads();

    if (tid == 0) {
        int flag = 0; unsigned u_lo = 0;
        if (total > (unsigned)CCAP) {
            int seg = s_seg;
            unsigned running = (seg < 1023) ? part[seg+1] : 0u;
            int bin = -1; unsigned cnt = 0;
            for (int j = 63; j >= 0; j--) {
                running += hist[seg*64 + j];
                if (running >= need) { bin = seg*64 + j; cnt = running; break; }
            }
            if (bin <= 0 || cnt > (unsigned)CCAP) flag = 1;
            else u_lo = (((unsigned)bin) << 12) | ULIM;
        }
        g_ulo[b] = u_lo;
        g_flag[b] = flag;
        g_compcnt[b] = 0;
    }
}

// ---------------- parallel compaction ----------------
__global__ void compact_kernel() {
    int b = blockIdx.y;
    if (g_flag[b]) return;
    int n = g_ccnt[b]; if (n > CAP) n = CAP;
    unsigned u_lo = g_ulo[b];
    const ull* ck = g_ckey + (size_t)b*CAP;
    int tid = threadIdx.x;
    int lane = tid & 31;
    int stride = gridDim.x * blockDim.x;
    int iters = (n + stride - 1) / stride;
    for (int j = 0; j < iters; j++) {
        int i = blockIdx.x*blockDim.x + tid + j*stride;
        ull k = 0; bool take = false;
        if (i < n) {
            k = ck[i];
            take = ((unsigned)(k >> 32)) >= u_lo;
        }
        unsigned m = __ballot_sync(0xFFFFFFFFu, take);
        if (m) {
            int leader = __ffs(m) - 1;
            int cnt = __popc(m);
            int base = 0;
            if (lane == leader) base = atomicAdd(&g_compcnt[b], cnt);
            base = __shfl_sync(0xFFFFFFFFu, base, leader);
            if (take) {
                int p = base + __popc(m & ((1u << lane) - 1));
                if (p < SORTN) g_comp[b*SORTN + p] = k;
            }
        }
    }
}

// ---------------- per-batch sort (+ exact fallback) ----------------
__global__ void __launch_bounds__(1024) sort_kernel() {
    extern __shared__ ull keys[];
    __shared__ unsigned fhist[2048];
    __shared__ ull s_hi;
    __shared__ int s_need, s_bin, s_cnt2;

    int b = blockIdx.x, tid = threadIdx.x;

    if (!g_flag[b]) {
        int M = g_compcnt[b]; if (M > SORTN) M = SORTN;
        for (int i = tid; i < SORTN; i += 1024)
            keys[i] = (i < M) ? g_comp[b*SORTN + i]
                              : (ull)(0xFFFFFFFFu - (unsigned)(i - M));
        __syncthreads();
        for (int k = 2; k <= SORTN; k <<= 1) {
            for (int j = k >> 1; j > 0; j >>= 1) {
                for (int t = tid; t < SORTN; t += 1024) {
                    int p = t ^ j;
                    if (p > t) {
                        ull a = keys[t], c2 = keys[p];
                        bool asc = ((t & k) == 0);
                        if ((a > c2) == asc) { keys[t] = c2; keys[p] = a; }
                    }
                }
                __syncthreads();
            }
        }
        for (int i = tid; i < TOPK; i += 1024) {
            ull c = keys[SORTN-1-i];
            g_topk[b*TOPK + i] = (int)(0xFFFFFFFFu - (unsigned)(c & 0xFFFFFFFFull));
        }
        return;
    }

    // fallback: exact 6-level radix select
    int n = g_ccnt[b]; if (n > CAP) n = CAP;
    const ull* ck = g_ckey + (size_t)b*CAP;
    if (tid == 0) { s_hi = 0ull; s_need = TOPK; }
    __syncthreads();
    const int shifts[6] = {53, 42, 32, 21, 10, 0};
    const int nbits [6] = {11, 11, 10, 11, 11, 10};
    for (int lvl = 0; lvl < 6; lvl++) {
        int nb = nbits[lvl], sh = shifts[lvl], nbin = 1 << nb;
        for (int i = tid; i < nbin; i += 1024) fhist[i] = 0;
        __syncthreads();
        ull hi = s_hi;
        for (int i = tid; i < n; i += 1024) {
            ull c = ck[i];
            if ((c >> (sh + nb)) == hi)
                atomicAdd(&fhist[(unsigned)((c >> sh) & (ull)(nbin-1))], 1u);
        }
        __syncthreads();
        for (int off = 1; off < nbin; off <<= 1) {
            unsigned a0 = 0, a1 = 0;
            int i0 = tid, i1 = tid + 1024;
            if (i0 < nbin) a0 = fhist[i0] + ((i0+off < nbin) ? fhist[i0+off] : 0u);
            if (i1 < nbin) a1 = fhist[i1] + ((i1+off < nbin) ? fhist[i1+off] : 0u);
            __syncthreads();
            if (i0 < nbin) fhist[i0] = a0;
            if (i1 < nbin) fhist[i1] = a1;
            __syncthreads();
        }
        if (tid == 0) s_bin = -1;
        __syncthreads();
        int need = s_need;
        for (int i = tid; i < nbin; i += 1024) {
            unsigned Si = fhist[i];
            unsigned Sn = (i+1 < nbin) ? fhist[i+1] : 0u;
            if (Si >= (unsigned)need && Sn < (unsigned)need) s_bin = i;
        }
        __syncthreads();
        if (tid == 0) {
            int bin = s_bin;
            if (bin < 0) { bin = 0; s_need = (int)fhist[0]; }
            else {
                unsigned above = (bin+1 < nbin) ? fhist[bin+1] : 0u;
                s_need = s_need - (int)above;
            }
            s_hi = (s_hi << nb) | (ull)(unsigned)bin;
        }
        __syncthreads();
    }
    ull T = s_hi;
    if (tid == 0) s_cnt2 = 0;
    __syncthreads();
    for (int i = tid; i < n; i += 1024) {
        ull c = ck[i];
        if (c >= T) {
            int p = atomicAdd(&s_cnt2, 1);
            if (p < TOPK) keys[p] = c;
        }
    }
    __syncthreads();
    int cnt = s_cnt2; if (cnt > TOPK) cnt = TOPK;
    for (int i = tid; i < TOPK; i += 1024)
        if (i >= cnt) keys[i] = (ull)(0xFFFFFFFFu - (unsigned)i);
    __syncthreads();
    for (int k = 2; k <= TOPK; k <<= 1) {
        for (int j = k >> 1; j > 0; j >>= 1) {
            for (int t = tid; t < TOPK; t += 1024) {
                int p = t ^ j;
                if (p > t) {
                    ull a = keys[t], c2 = keys[p];
                    bool asc = ((t & k) == 0);
                    if ((a > c2) == asc) { keys[t] = c2; keys[p] = a; }
                }
            }
            __syncthreads();
        }
    }
    for (int i = tid; i < TOPK; i += 1024) {
        ull c = keys[TOPK-1-i];
        g_topk[b*TOPK + i] = (int)(0xFFFFFFFFu - (unsigned)(c & 0xFFFFFFFFull));
    }
}

// ---------------- refinement ----------------
__device__ __forceinline__ float bil_tap(const float* img, float xf, float yf, float wgt) {
    bool valid = (xf >= 0.f) & (xf < (float)W) & (yf >= 0.f) & (yf < (float)H);
    int xc = (int)fminf(fmaxf(xf, 0.f), (float)(W-1));
    int yc = (int)fminf(fmaxf(yf, 0.f), (float)(H-1));
    float s = valid ? img[yc*W + xc] : 0.f;
    return s * wgt;
}

__global__ void refine_kernel(const float* __restrict__ S, float* __restrict__ out) {
    int g = blockIdx.x * blockDim.x + threadIdx.x;
    if (g >= BATCH*TOPK) return;
    int b = g / TOPK;
    int idx = g_topk[g];
    int ix = idx & (W-1), iy = idx >> 10;
    const float* img = S + (size_t)b*NPIX;

    float v[25];
    float mx = -1e30f;
    #pragma unroll
    for (int dy = 0; dy < 5; dy++) {
        int y = iy + dy - 2;
        #pragma unroll
        for (int dx = 0; dx < 5; dx++) {
            int x = ix + dx - 2;
            float val = (y >= 0 && y < H && x >= 0 && x < W) ? __ldg(img + y*W + x) : 0.f;
            v[dy*5 + dx] = val;
            mx = fmaxf(mx, val);
        }
    }
    float e[25];
    float S0 = 0.f, Sx = 0.f, Sy = 0.f;
    #pragma unroll
    for (int p = 0; p < 25; p++) {
        float ee = expf((v[p] - mx) * 10.0f);
        e[p] = ee;
        S0 += ee;
        Sx += ee * (float)(p % 5 - 2);
        Sy += ee * (float)(p / 5 - 2);
    }
    float rx = Sx / S0, ry = Sy / S0;
    float disp = 0.f;
    #pragma unroll
    for (int p = 0; p < 25; p++) {
        float ddx = ((float)(p % 5 - 2) - rx) * 0.5f;
        float ddy = ((float)(p / 5 - 2) - ry) * 0.5f;
        disp += e[p] * (ddx*ddx + ddy*ddy);
    }
    disp /= S0;

    float kx = ((float)ix + rx) / (float)(W-1) * 2.f - 1.f;
    float ky = ((float)iy + ry) / (float)(H-1) * 2.f - 1.f;

    float px = (kx + 1.f) * 0.5f * (float)(W-1);
    float py = (ky + 1.f) * 0.5f * (float)(H-1);
    float x0 = floorf(px), y0 = floorf(py);
    float wx1 = px - x0, wx0 = 1.f - wx1;
    float wy1 = py - y0, wy0 = 1.f - wy1;
    float score = bil_tap(img, x0,     y0,     wx0*wy0)
                + bil_tap(img, x0+1.f, y0,     wx1*wy0)
                + bil_tap(img, x0,     y0+1.f, wx0*wy1)
                + bil_tap(img, x0+1.f, y0+1.f, wx1*wy1);

    out[2*g + 0] = kx;
    out[2*g + 1] = ky;
    out[BATCH*TOPK*2 + g] = score;
    out[BATCH*TOPK*3 + g] = disp;
}

// ---------------- launch ----------------
extern "C" void kernel_launch(void* const* d_in, const int* in_sizes, int n_in,
                              void* d_out, int out_size) {
    const float* S = (const float*)d_in[0];
    float* out = (float*)d_out;

    const int nms_smem  = 3*RS2*sizeof(float) + 2*RS2;   // 98784
    const int sort_smem = SORTN*sizeof(ull);             // 65536
    static int attr_set = 0;
    if (!attr_set) {
        cudaFuncSetAttribute(nms_fused, cudaFuncAttributeMaxDynamicSharedMemorySize, nms_smem);
        cudaFuncSetAttribute(sort_kernel, cudaFuncAttributeMaxDynamicSharedMemorySize, sort_smem);
        attr_set = 1;
    }

    reset_kernel<<<128, 1024>>>();
    dim3 grid(16, 16, 8);
    nms_fused<<<grid, NT, nms_smem>>>(S);
    threshold_kernel<<<BATCH, 1024>>>();
    compact_kernel<<<dim3(64, BATCH), 256>>>();
    sort_kernel<<<BATCH, 1024, sort_smem>>>();
    refine_kernel<<<(BATCH*TOPK + 255) / 256, 256>>>(S, out);
}

// round 6
// speedup vs baseline: 4.2897x; 1.2480x over previous
#include <cuda_runtime.h>
#include <math.h>

#define BATCH 8
#define H 1024
#define W 1024
#define NPIX (H*W)
#define TOPK 4096
#define CAP  262144
#define RS   84           // 64 tile + 2*10 halo
#define RS2  (RS*RS)
#define NT   512
#define NBIN 65536
#define CCAP 6144
#define SORTN 8192
#define ULIM 0x30000000u
#define LISTCAP 512

typedef unsigned long long ull;
typedef unsigned int uint;

// ---------------- scratch ----------------
__device__ ull      g_ckey[(size_t)BATCH*CAP];
__device__ int      g_ccnt[BATCH];
__device__ unsigned g_hist[BATCH*NBIN];
__device__ ull      g_comp[BATCH*SORTN];
__device__ int      g_compcnt[BATCH];
__device__ unsigned g_ulo[BATCH];
__device__ int      g_flag[BATCH];
__device__ int      g_topk[BATCH*TOPK];

__global__ void reset_hist_kernel() {
    int i = blockIdx.x*1024 + threadIdx.x;
    uint4* h4 = (uint4*)g_hist;
    if (i < BATCH*NBIN/4) h4[i] = make_uint4(0,0,0,0);
}
__global__ void reset_cnt_kernel() {
    if (threadIdx.x < BATCH) g_ccnt[threadIdx.x] = 0;
}
__global__ void noop_kernel() {}

// ---------------- fused NMS ----------------
// horizontal 5-tap max over floats (LO in {2})
template<int LO>
__device__ __forceinline__ void hmax_f4(const float* __restrict__ src,
                                        float* __restrict__ dst, int tid) {
    static_assert((LO & 3) == 2, "alignment");
    constexpr int Wd = RS - 2*LO;
    constexpr int NC = Wd/4;
    constexpr int YN = Wd + 4;
    for (int c = tid; c < YN*NC; c += NT) {
        int ry = (LO-2) + c / NC;
        int cx = LO + (c % NC)*4;
        const float* p = src + ry*RS + (cx-2);
        float4 A = *(const float4*)p;
        float4 B = *(const float4*)(p+4);
        float m12 = fmaxf(A.y, A.z);
        float m34 = fmaxf(A.w, B.x);
        float m56 = fmaxf(B.y, B.z);
        float* q = dst + ry*RS + cx;
        *(float2*)q     = make_float2(fmaxf(fmaxf(A.x, m12), m34),
                                      fmaxf(fmaxf(m12, m34), B.y));
        *(float2*)(q+2) = make_float2(fmaxf(fmaxf(A.z, m34), m56),
                                      fmaxf(fmaxf(m34, m56), B.w));
    }
}

// horizontal 5-tap max over masked field (sU ? 0 : sS), LO in {6, 10}
template<int LO>
__device__ __forceinline__ void hmax_fm4(const float* __restrict__ sS,
                                         const unsigned char* __restrict__ sU,
                                         float* __restrict__ dst, int tid) {
    static_assert((LO & 3) == 2, "alignment");
    constexpr int Wd = RS - 2*LO;
    constexpr int NC = Wd/4;
    constexpr int YN = Wd + 4;
    for (int c = tid; c < YN*NC; c += NT) {
        int ry = (LO-2) + c / NC;
        int cx = LO + (c % NC)*4;
        int base = ry*RS + (cx-2);
        float4 A = *(const float4*)(sS + base);
        float4 B = *(const float4*)(sS + base + 4);
        uint u0 = *(const uint*)(sU + base);
        uint u1 = *(const uint*)(sU + base + 4);
        float v0 = (u0 & 0x000000FFu) ? 0.f : A.x;
        float v1 = (u0 & 0x0000FF00u) ? 0.f : A.y;
        float v2 = (u0 & 0x00FF0000u) ? 0.f : A.z;
        float v3 = (u0 & 0xFF000000u) ? 0.f : A.w;
        float v4 = (u1 & 0x000000FFu) ? 0.f : B.x;
        float v5 = (u1 & 0x0000FF00u) ? 0.f : B.y;
        float v6 = (u1 & 0x00FF0000u) ? 0.f : B.z;
        float v7 = (u1 & 0xFF000000u) ? 0.f : B.w;
        float m12 = fmaxf(v1, v2);
        float m34 = fmaxf(v3, v4);
        float m56 = fmaxf(v5, v6);
        float* q = dst + ry*RS + cx;
        *(float2*)q     = make_float2(fmaxf(fmaxf(v0, m12), m34),
                                      fmaxf(fmaxf(m12, m34), v5));
        *(float2*)(q+2) = make_float2(fmaxf(fmaxf(v2, m34), m56),
                                      fmaxf(fmaxf(m34, m56), v7));
    }
}

// horizontal 5-tap OR over 0/1 bytes, LO in {4, 8}
template<int LO>
__device__ __forceinline__ void hmax_b4(const unsigned char* __restrict__ src,
                                        unsigned char* __restrict__ dst, int tid) {
    static_assert((LO & 3) == 0, "alignment");
    constexpr int Wd = RS - 2*LO;
    constexpr int NC = Wd/4;
    constexpr int YN = Wd + 4;
    for (int c = tid; c < YN*NC; c += NT) {
        int ry = (LO-2) + c / NC;
        int cx = LO + (c % NC)*4;
        int base = ry*RS + cx;
        uint W0 = *(const uint*)(src + base - 4);
        uint W1 = *(const uint*)(src + base);
        uint W2 = *(const uint*)(src + base + 4);
        uint v1 = __byte_perm(W0, W1, 0x5432);
        uint v2 = __byte_perm(W0, W1, 0x6543);
        uint v4 = __byte_perm(W1, W2, 0x4321);
        uint v5 = __byte_perm(W1, W2, 0x5432);
        *(uint*)(dst + base) = v1 | v2 | W1 | v4 | v5;
    }
}

#define VTREE_F(t, o) do { \
    float m12 = fmaxf(t[1], t[2]); \
    float m34 = fmaxf(t[3], t[4]); \
    float m56 = fmaxf(t[5], t[6]); \
    o[0] = fmaxf(fmaxf(t[0], m12), m34); \
    o[1] = fmaxf(fmaxf(m12, m34), t[5]); \
    o[2] = fmaxf(fmaxf(t[2], m34), m56); \
    o[3] = fmaxf(fmaxf(m34, m56), t[7]); \
} while(0)

__global__ __launch_bounds__(NT, 3) void nms_fused(const float* __restrict__ S) {
    extern __shared__ float sh[];
    float* sS = sh;                       // scores (0 outside image)
    float* sT = sh + RS2;                 // separable temp (aliased for byte stages)
    unsigned char* sTb = (unsigned char*)sT;
    unsigned char* sM = (unsigned char*)(sh + 2*RS2);   // mask
    unsigned char* sU = sM + RS2;                       // supp
    ull* sList = (ull*)(sM + 2*RS2);                    // candidate list
    __shared__ int s_cnt, s_base;

    int tid = threadIdx.x;
    int b = blockIdx.z;
    int tx0 = blockIdx.x*64 - 10, ty0 = blockIdx.y*64 - 10;
    const float* img = S + (size_t)b*NPIX;

    bool interior = (blockIdx.x >= 1) & (blockIdx.x <= 14) &
                    (blockIdx.y >= 1) & (blockIdx.y <= 14);
    if (interior) {
        const float* rowbase = img + (size_t)ty0*W + (tx0 - 2);   // 16B aligned
        for (int i = tid; i < 84*22; i += NT) {
            int ry = i / 22, k = i - ry*22;
            float4 v = __ldg((const float4*)(rowbase + (size_t)ry*W) + k);
            int rx0 = 4*k - 2;
            float* q = sS + ry*RS + rx0;
            if (k > 0)  *(float2*)q     = make_float2(v.x, v.y);
            if (k < 21) *(float2*)(q+2) = make_float2(v.z, v.w);
        }
    } else {
        for (int i = tid; i < RS2; i += NT) {
            int ry = i/RS, rx = i - ry*RS;
            int gx = tx0+rx, gy = ty0+ry;
            bool in = ((unsigned)gx < W) & ((unsigned)gy < H);
            sS[i] = in ? __ldg(img + gy*W + gx) : 0.f;
        }
    }
    if (tid == 0) s_cnt = 0;
    __syncthreads();

    // ---- stage 1: m0 = in && (S == maxpool(S)) ----
    hmax_f4<2>(sS, sT, tid); __syncthreads();
    {
        constexpr int LO = 2, Wd = RS - 2*LO;
        for (int c = tid; c < Wd*(Wd/4); c += NT) {
            int rx = LO + c % Wd;
            int ry0 = LO + (c / Wd)*4;
            float t[8], o[4];
            #pragma unroll
            for (int r = 0; r < 8; r++) t[r] = sT[(ry0-2+r)*RS + rx];
            VTREE_F(t, o);
            bool inx = ((unsigned)(tx0+rx) < W);
            #pragma unroll
            for (int r = 0; r < 4; r++) {
                int idx = (ry0+r)*RS + rx;
                bool in = inx & ((unsigned)(ty0+ry0+r) < H);
                sM[idx] = (unsigned char)(in && (sS[idx] == o[r]));
            }
        }
    }
    __syncthreads();

    // ---- stage 2: supp1 = dilate(m0)  (ss1 recomputed on the fly later) ----
    hmax_b4<4>(sM, sTb, tid); __syncthreads();
    {
        constexpr int LO = 4, Wd = RS - 2*LO;
        for (int c = tid; c < Wd*(Wd/4); c += NT) {
            int rx = LO + c % Wd;
            int ry0 = LO + (c / Wd)*4;
            unsigned t[8];
            #pragma unroll
            for (int r = 0; r < 8; r++) t[r] = sTb[(ry0-2+r)*RS + rx];
            unsigned m12 = t[1]|t[2], m34 = t[3]|t[4], m56 = t[5]|t[6];
            unsigned o[4] = { t[0]|m12|m34, m12|m34|t[5], t[2]|m34|m56, m34|m56|t[7] };
            #pragma unroll
            for (int r = 0; r < 4; r++)
                sU[(ry0+r)*RS + rx] = (unsigned char)(o[r] != 0u);
        }
    }
    __syncthreads();

    // ---- stage 3: mask1 = m0 | ((ss1 == maxpool(ss1)) & ~supp1) ----
    hmax_fm4<6>(sS, sU, sT, tid); __syncthreads();
    {
        constexpr int LO = 6, Wd = RS - 2*LO;
        for (int c = tid; c < Wd*(Wd/4); c += NT) {
            int rx = LO + c % Wd;
            int ry0 = LO + (c / Wd)*4;
            float t[8], o[4];
            #pragma unroll
            for (int r = 0; r < 8; r++) t[r] = sT[(ry0-2+r)*RS + rx];
            VTREE_F(t, o);
            bool inx = ((unsigned)(tx0+rx) < W);
            #pragma unroll
            for (int r = 0; r < 4; r++) {
                int idx = (ry0+r)*RS + rx;
                bool in = inx & ((unsigned)(ty0+ry0+r) < H);
                bool u = sU[idx] != 0;
                float f = u ? 0.f : sS[idx];
                bool nw = (f == o[r]) && !u;
                sM[idx] = (unsigned char)(in && (sM[idx] || nw));
            }
        }
    }
    __syncthreads();

    // ---- stage 4: supp2 = dilate(mask1) ----
    hmax_b4<8>(sM, sTb, tid); __syncthreads();
    {
        constexpr int LO = 8, Wd = RS - 2*LO;
        for (int c = tid; c < Wd*(Wd/4); c += NT) {
            int rx = LO + c % Wd;
            int ry0 = LO + (c / Wd)*4;
            unsigned t[8];
            #pragma unroll
            for (int r = 0; r < 8; r++) t[r] = sTb[(ry0-2+r)*RS + rx];
            unsigned m12 = t[1]|t[2], m34 = t[3]|t[4], m56 = t[5]|t[6];
            unsigned o[4] = { t[0]|m12|m34, m12|m34|t[5], t[2]|m34|m56, m34|m56|t[7] };
            #pragma unroll
            for (int r = 0; r < 4; r++)
                sU[(ry0+r)*RS + rx] = (unsigned char)(o[r] != 0u);
        }
    }
    __syncthreads();

    // ---- stage 5: final mask + border + candidates + histogram ----
    hmax_fm4<10>(sS, sU, sT, tid); __syncthreads();
    {
        constexpr int LO = 10, Wd = RS - 2*LO;   // 64
        for (int c = tid; c < Wd*(Wd/4); c += NT) {
            int rx = LO + c % Wd;
            int ry0 = LO + (c / Wd)*4;
            float t[8], o[4];
            #pragma unroll
            for (int r = 0; r < 8; r++) t[r] = sT[(ry0-2+r)*RS + rx];
            VTREE_F(t, o);
            int gx = tx0 + rx;
            bool bx = (gx < 2) | (gx >= W-2);
            #pragma unroll
            for (int r = 0; r < 4; r++) {
                int idx = (ry0+r)*RS + rx;
                float s = sS[idx];
                bool u = sU[idx] != 0;
                float f = u ? 0.f : s;
                bool nw = (f == o[r]) && !u;
                bool m = sM[idx] || nw;
                int gy = ty0 + ry0 + r;
                bool border = bx | (gy < 2) | (gy >= H-2);
                if (m & !border & (s > 0.f)) {
                    unsigned ub = __float_as_uint(s);
                    unsigned bin = (ub >= ULIM) ? ((ub >> 12) & 0xFFFFu) : 0u;
                    atomicAdd(&g_hist[b*NBIN + bin], 1u);
                    ull key = ((ull)ub << 32) |
                              (ull)(0xFFFFFFFFu - (unsigned)(gy*W + gx));
                    int p = atomicAdd(&s_cnt, 1);
                    if (p < LISTCAP) sList[p] = key;
                    else {
                        int q = atomicAdd(&g_ccnt[b], 1);
                        if (q < CAP) g_ckey[(size_t)b*CAP + q] = key;
                    }
                }
            }
        }
        __syncthreads();
        if (tid == 0) {
            int c2 = s_cnt < LISTCAP ? s_cnt : LISTCAP;
            s_base = atomicAdd(&g_ccnt[b], c2);
            s_cnt = c2;
        }
        __syncthreads();
        int c2 = s_cnt, base = s_base;
        for (int i = tid; i < c2; i += NT) {
            int q = base + i;
            if (q < CAP) g_ckey[(size_t)b*CAP + q] = sList[i];
        }
    }
}

// ---------------- per-batch exact threshold from histogram ----------------
__global__ void __launch_bounds__(1024) threshold_kernel() {
    __shared__ unsigned part[1024];
    __shared__ int s_seg;
    int b = blockIdx.x, tid = threadIdx.x;
    const unsigned* hist = g_hist + b*NBIN;

    unsigned s = 0;
    const uint4* h4 = (const uint4*)hist + tid*16;
    #pragma unroll
    for (int j = 0; j < 16; j++) {
        uint4 w = h4[j];
        s += w.x + w.y + w.z + w.w;
    }
    part[tid] = s;
    __syncthreads();
    for (int off = 1; off < 1024; off <<= 1) {
        unsigned v = part[tid] + ((tid+off < 1024) ? part[tid+off] : 0u);
        __syncthreads();
        part[tid] = v;
        __syncthreads();
    }
    unsigned total = part[0];
    unsigned need = total < (unsigned)TOPK ? total : (unsigned)TOPK;

    if (tid == 0) s_seg = -1;
    __syncthreads();
    if (total > (unsigned)CCAP) {
        if (part[tid] >= need && (tid == 1023 || part[tid+1] < need)) s_seg = tid;
    }
    __syncthreads();

    if (tid == 0) {
        int flag = 0; unsigned u_lo = 0;
        if (total > (unsigned)CCAP) {
            int seg = s_seg;
            unsigned running = (seg < 1023) ? part[seg+1] : 0u;
            int bin = -1; unsigned cnt = 0;
            for (int j = 63; j >= 0; j--) {
                running += hist[seg*64 + j];
                if (running >= need) { bin = seg*64 + j; cnt = running; break; }
            }
            if (bin <= 0 || cnt > (unsigned)CCAP) flag = 1;
            else u_lo = (((unsigned)bin) << 12) | ULIM;
        }
        g_ulo[b] = u_lo;
        g_flag[b] = flag;
        g_compcnt[b] = 0;
    }
}

// ---------------- parallel compaction ----------------
__global__ void compact_kernel() {
    int b = blockIdx.y;
    if (g_flag[b]) return;
    int n = g_ccnt[b]; if (n > CAP) n = CAP;
    unsigned u_lo = g_ulo[b];
    const ull* ck = g_ckey + (size_t)b*CAP;
    int tid = threadIdx.x;
    int lane = tid & 31;
    int stride = gridDim.x * blockDim.x;
    int iters = (n + stride - 1) / stride;
    for (int j = 0; j < iters; j++) {
        int i = blockIdx.x*blockDim.x + tid + j*stride;
        ull k = 0; bool take = false;
        if (i < n) {
            k = ck[i];
            take = ((unsigned)(k >> 32)) >= u_lo;
        }
        unsigned m = __ballot_sync(0xFFFFFFFFu, take);
        if (m) {
            int leader = __ffs(m) - 1;
            int cnt = __popc(m);
            int base = 0;
            if (lane == leader) base = atomicAdd(&g_compcnt[b], cnt);
            base = __shfl_sync(0xFFFFFFFFu, base, leader);
            if (take) {
                int p = base + __popc(m & ((1u << lane) - 1));
                if (p < SORTN) g_comp[b*SORTN + p] = k;
            }
        }
    }
}

// ---------------- per-batch sort (+ exact fallback) ----------------
__global__ void __launch_bounds__(1024) sort_kernel() {
    extern __shared__ ull keys[];
    __shared__ unsigned fhist[2048];
    __shared__ ull s_hi;
    __shared__ int s_need, s_bin, s_cnt2;

    int b = blockIdx.x, tid = threadIdx.x;

    if (!g_flag[b]) {
        int M = g_compcnt[b]; if (M > SORTN) M = SORTN;
        for (int i = tid; i < SORTN; i += 1024)
            keys[i] = (i < M) ? g_comp[b*SORTN + i]
                              : (ull)(0xFFFFFFFFu - (unsigned)(i - M));
        __syncthreads();
        for (int k = 2; k <= SORTN; k <<= 1) {
            for (int j = k >> 1; j > 0; j >>= 1) {
                for (int t = tid; t < SORTN; t += 1024) {
                    int p = t ^ j;
                    if (p > t) {
                        ull a = keys[t], c2 = keys[p];
                        bool asc = ((t & k) == 0);
                        if ((a > c2) == asc) { keys[t] = c2; keys[p] = a; }
                    }
                }
                __syncthreads();
            }
        }
        for (int i = tid; i < TOPK; i += 1024) {
            ull c = keys[SORTN-1-i];
            g_topk[b*TOPK + i] = (int)(0xFFFFFFFFu - (unsigned)(c & 0xFFFFFFFFull));
        }
        return;
    }

    // fallback: exact 6-level radix select
    int n = g_ccnt[b]; if (n > CAP) n = CAP;
    const ull* ck = g_ckey + (size_t)b*CAP;
    if (tid == 0) { s_hi = 0ull; s_need = TOPK; }
    __syncthreads();
    const int shifts[6] = {53, 42, 32, 21, 10, 0};
    const int nbits [6] = {11, 11, 10, 11, 11, 10};
    for (int lvl = 0; lvl < 6; lvl++) {
        int nb = nbits[lvl], sh = shifts[lvl], nbin = 1 << nb;
        for (int i = tid; i < nbin; i += 1024) fhist[i] = 0;
        __syncthreads();
        ull hi = s_hi;
        for (int i = tid; i < n; i += 1024) {
            ull c = ck[i];
            if ((c >> (sh + nb)) == hi)
                atomicAdd(&fhist[(unsigned)((c >> sh) & (ull)(nbin-1))], 1u);
        }
        __syncthreads();
        for (int off = 1; off < nbin; off <<= 1) {
            unsigned a0 = 0, a1 = 0;
            int i0 = tid, i1 = tid + 1024;
            if (i0 < nbin) a0 = fhist[i0] + ((i0+off < nbin) ? fhist[i0+off] : 0u);
            if (i1 < nbin) a1 = fhist[i1] + ((i1+off < nbin) ? fhist[i1+off] : 0u);
            __syncthreads();
            if (i0 < nbin) fhist[i0] = a0;
            if (i1 < nbin) fhist[i1] = a1;
            __syncthreads();
        }
        if (tid == 0) s_bin = -1;
        __syncthreads();
        int need = s_need;
        for (int i = tid; i < nbin; i += 1024) {
            unsigned Si = fhist[i];
            unsigned Sn = (i+1 < nbin) ? fhist[i+1] : 0u;
            if (Si >= (unsigned)need && Sn < (unsigned)need) s_bin = i;
        }
        __syncthreads();
        if (tid == 0) {
            int bin = s_bin;
            if (bin < 0) { bin = 0; s_need = (int)fhist[0]; }
            else {
                unsigned above = (bin+1 < nbin) ? fhist[bin+1] : 0u;
                s_need = s_need - (int)above;
            }
            s_hi = (s_hi << nb) | (ull)(unsigned)bin;
        }
        __syncthreads();
    }
    ull T = s_hi;
    if (tid == 0) s_cnt2 = 0;
    __syncthreads();
    for (int i = tid; i < n; i += 1024) {
        ull c = ck[i];
        if (c >= T) {
            int p = atomicAdd(&s_cnt2, 1);
            if (p < TOPK) keys[p] = c;
        }
    }
    __syncthreads();
    int cnt = s_cnt2; if (cnt > TOPK) cnt = TOPK;
    for (int i = tid; i < TOPK; i += 1024)
        if (i >= cnt) keys[i] = (ull)(0xFFFFFFFFu - (unsigned)i);
    __syncthreads();
    for (int k = 2; k <= TOPK; k <<= 1) {
        for (int j = k >> 1; j > 0; j >>= 1) {
            for (int t = tid; t < TOPK; t += 1024) {
                int p = t ^ j;
                if (p > t) {
                    ull a = keys[t], c2 = keys[p];
                    bool asc = ((t & k) == 0);
                    if ((a > c2) == asc) { keys[t] = c2; keys[p] = a; }
                }
            }
            __syncthreads();
        }
    }
    for (int i = tid; i < TOPK; i += 1024) {
        ull c = keys[TOPK-1-i];
        g_topk[b*TOPK + i] = (int)(0xFFFFFFFFu - (unsigned)(c & 0xFFFFFFFFull));
    }
}

// ---------------- refinement ----------------
__device__ __forceinline__ float bil_tap(const float* img, float xf, float yf, float wgt) {
    bool valid = (xf >= 0.f) & (xf < (float)W) & (yf >= 0.f) & (yf < (float)H);
    int xc = (int)fminf(fmaxf(xf, 0.f), (float)(W-1));
    int yc = (int)fminf(fmaxf(yf, 0.f), (float)(H-1));
    float s = valid ? img[yc*W + xc] : 0.f;
    return s * wgt;
}

__global__ void refine_kernel(const float* __restrict__ S, float* __restrict__ out) {
    int g = blockIdx.x * blockDim.x + threadIdx.x;
    if (g >= BATCH*TOPK) return;
    int b = g / TOPK;
    int idx = g_topk[g];
    int ix = idx & (W-1), iy = idx >> 10;
    const float* img = S + (size_t)b*NPIX;

    float v[25];
    float mx = -1e30f;
    #pragma unroll
    for (int dy = 0; dy < 5; dy++) {
        int y = iy + dy - 2;
        #pragma unroll
        for (int dx = 0; dx < 5; dx++) {
            int x = ix + dx - 2;
            float val = (y >= 0 && y < H && x >= 0 && x < W) ? __ldg(img + y*W + x) : 0.f;
            v[dy*5 + dx] = val;
            mx = fmaxf(mx, val);
        }
    }
    float e[25];
    float S0 = 0.f, Sx = 0.f, Sy = 0.f;
    #pragma unroll
    for (int p = 0; p < 25; p++) {
        float ee = expf((v[p] - mx) * 10.0f);
        e[p] = ee;
        S0 += ee;
        Sx += ee * (float)(p % 5 - 2);
        Sy += ee * (float)(p / 5 - 2);
    }
    float rx = Sx / S0, ry = Sy / S0;
    float disp = 0.f;
    #pragma unroll
    for (int p = 0; p < 25; p++) {
        float ddx = ((float)(p % 5 - 2) - rx) * 0.5f;
        float ddy = ((float)(p / 5 - 2) - ry) * 0.5f;
        disp += e[p] * (ddx*ddx + ddy*ddy);
    }
    disp /= S0;

    float kx = ((float)ix + rx) / (float)(W-1) * 2.f - 1.f;
    float ky = ((float)iy + ry) / (float)(H-1) * 2.f - 1.f;

    float px = (kx + 1.f) * 0.5f * (float)(W-1);
    float py = (ky + 1.f) * 0.5f * (float)(H-1);
    float x0 = floorf(px), y0 = floorf(py);
    float wx1 = px - x0, wx0 = 1.f - wx1;
    float wy1 = py - y0, wy0 = 1.f - wy1;
    float score = bil_tap(img, x0,     y0,     wx0*wy0)
                + bil_tap(img, x0+1.f, y0,     wx1*wy0)
                + bil_tap(img, x0,     y0+1.f, wx0*wy1)
                + bil_tap(img, x0+1.f, y0+1.f, wx1*wy1);

    out[2*g + 0] = kx;
    out[2*g + 1] = ky;
    out[BATCH*TOPK*2 + g] = score;
    out[BATCH*TOPK*3 + g] = disp;
}

// ---------------- launch ----------------
extern "C" void kernel_launch(void* const* d_in, const int* in_sizes, int n_in,
                              void* d_out, int out_size) {
    const float* S = (const float*)d_in[0];
    float* out = (float*)d_out;

    const int nms_smem  = 2*RS2*sizeof(float) + 2*RS2 + LISTCAP*sizeof(ull); // 74656
    const int sort_smem = SORTN*sizeof(ull);                                  // 65536
    static int attr_set = 0;
    if (!attr_set) {
        cudaFuncSetAttribute(nms_fused, cudaFuncAttributeMaxDynamicSharedMemorySize, nms_smem);
        cudaFuncSetAttribute(sort_kernel, cudaFuncAttributeMaxDynamicSharedMemorySize, sort_smem);
        attr_set = 1;
    }

    reset_hist_kernel<<<128, 1024>>>();   // launch 1
    reset_cnt_kernel<<<1, 32>>>();        // launch 2
    noop_kernel<<<1, 32>>>();             // launch 3 (pads nms to profiled slot #4)
    dim3 grid(16, 16, 8);
    nms_fused<<<grid, NT, nms_smem>>>(S); // launch 4  <-- profiled
    threshold_kernel<<<BATCH, 1024>>>();
    compact_kernel<<<dim3(64, BATCH), 256>>>();
    sort_kernel<<<BATCH, 1024, sort_smem>>>();
    refine_kernel<<<(BATCH*TOPK + 255) / 256, 256>>>(S, out);
}